// round 7
// baseline (speedup 1.0000x reference)
#include <cuda_runtime.h>
#include <math.h>

#define B 32
#define N 1024
#define D 2048   // IMG_DIM
#define E 1024   // EMBED
#define CHUNKS 32
#define CROWS (N / CHUNKS)   // 32 rows per chunk

// ---------------- scratch (device globals) ----------------
__device__ float g_v[B * D];
__device__ float g_scores[B * N];
__device__ float g_part[B * CHUNKS * D];     // 8MB
__device__ float g_pm[B * CHUNKS];
__device__ float g_pl[B * CHUNKS];
__device__ float g_x[B * D];
__device__ float g_outfeat[B * E];
__device__ float g_feats[B * E];

// ---------------- K0a: zero g_v (before k1) ----------------
__global__ void k0a_zero() {
    int i = blockIdx.x * 256 + threadIdx.x;      // B*D = 65536
    g_v[i] = 0.0f;
}
// ---------------- K0b: bias init (before k5/k6) ----------------
__global__ void k0b_bias(const float* __restrict__ ws1_b, const float* __restrict__ fc_b) {
    int i = blockIdx.x * 256 + threadIdx.x;      // 2*B*E = 65536
    if (i < B * E) g_outfeat[i] = ws1_b[i & (E - 1)];
    else           g_feats[i - B * E] = fc_b[i & (E - 1)];
}

// ---------------- K1: v[b,d] += sum_e cap[b,e]*W1[e,d] ----------------
#define K1_EC 64
__global__ __launch_bounds__(128) void k1_v(const float* __restrict__ cap,
                                            const float* __restrict__ W1) {
    __shared__ float sc[16][K1_EC];
    int tid = threadIdx.x;
    int d  = blockIdx.x * 512 + tid * 4;
    int e0 = blockIdx.y * K1_EC;
    int b0 = blockIdx.z * 16;
    for (int i = tid; i < 16 * K1_EC; i += 128)
        sc[i >> 6][i & 63] = cap[(b0 + (i >> 6)) * E + e0 + (i & 63)];
    __syncthreads();
    float4 acc[16];
#pragma unroll
    for (int r = 0; r < 16; r++) acc[r] = make_float4(0.f, 0.f, 0.f, 0.f);
#pragma unroll 2
    for (int e = 0; e < K1_EC; e++) {
        float4 wv = *(const float4*)(W1 + (size_t)(e0 + e) * D + d);
#pragma unroll
        for (int r = 0; r < 16; r++) {
            float c = sc[r][e];
            acc[r].x += c * wv.x; acc[r].y += c * wv.y;
            acc[r].z += c * wv.z; acc[r].w += c * wv.w;
        }
    }
#pragma unroll
    for (int r = 0; r < 16; r++) {
        float* p = &g_v[(size_t)(b0 + r) * D + d];
        atomicAdd(p + 0, acc[r].x); atomicAdd(p + 1, acc[r].y);
        atomicAdd(p + 2, acc[r].z); atomicAdd(p + 3, acc[r].w);
    }
}

// ---------------- K2: fused scores + chunk softmax + weighted pooling --------
// Block = (chunk, b), 256 threads = 8 warps, 32 rows/chunk.
// Phase 1: warp-per-row streaming dots (no sync in loop, high MLP).
// Phase 1.5: warp 0 reduces <=32 scores (max, exp, sum) with shuffles.
// Phase 2: warp owns a 256-float d-slice; re-walks 32 rows (L2-resident by
// construction: chip-wide churn between phase1 and phase2 of a row << L2).
__global__ __launch_bounds__(256) void k2_fused(const float* __restrict__ img,
                                                const int* __restrict__ len) {
    __shared__ float sv[D];            // 8KB
    __shared__ float ssc[CROWS];
    __shared__ float sw[CROWS];

    int chunk = blockIdx.x, b = blockIdx.y;
    int L  = __ldg(&len[b]);
    int n0 = chunk * CROWS;
    int tid = threadIdx.x, warp = tid >> 5, lane = tid & 31;

    if (n0 >= L) {
        if (tid == 0) { g_pm[b * CHUNKS + chunk] = -INFINITY; g_pl[b * CHUNKS + chunk] = 0.f; }
        return;
    }
    int nv = min(CROWS, L - n0);

    for (int i = tid; i < D / 4; i += 256)
        ((float4*)sv)[i] = ((const float4*)g_v)[b * (D / 4) + i];
    __syncthreads();

    const float4* sv4 = (const float4*)sv;
    const float4* imgb = (const float4*)(img + ((size_t)b * N + n0) * D);

    // ---- phase 1: dots (4 rows per warp, fully independent) ----
#pragma unroll
    for (int t = 0; t < 4; t++) {
        int rn = warp + 8 * t;
        if (rn < nv) {
            const float4* row = imgb + (size_t)rn * (D / 4);
            float dot = 0.f;
#pragma unroll
            for (int j = 0; j < 16; j++) {
                float4 r = row[j * 32 + lane];
                float4 v = sv4[j * 32 + lane];
                dot += r.x * v.x + r.y * v.y + r.z * v.z + r.w * v.w;
            }
#pragma unroll
            for (int o = 16; o; o >>= 1) dot += __shfl_xor_sync(0xffffffffu, dot, o);
            if (lane == 0) { ssc[rn] = dot; g_scores[b * N + n0 + rn] = dot; }
        }
    }
    __syncthreads();

    // ---- phase 1.5: warp 0 computes chunk max / exp weights / sum ----
    if (warp == 0) {
        float s = (lane < nv) ? ssc[lane] : -INFINITY;
        float m = s;
#pragma unroll
        for (int o = 16; o; o >>= 1) m = fmaxf(m, __shfl_xor_sync(0xffffffffu, m, o));
        float e = (lane < nv) ? __expf(s - m) : 0.f;
        sw[lane] = e;
        float l = e;
#pragma unroll
        for (int o = 16; o; o >>= 1) l += __shfl_xor_sync(0xffffffffu, l, o);
        if (lane == 0) { g_pm[b * CHUNKS + chunk] = m; g_pl[b * CHUNKS + chunk] = l; }
    }
    __syncthreads();

    // ---- phase 2: weighted accumulate; warp w owns float4 range [w*64, w*64+64) ----
    int base = warp * 64 + lane;                 // float4 index; pair at +32
    float4 a0 = make_float4(0.f, 0.f, 0.f, 0.f);
    float4 a1 = make_float4(0.f, 0.f, 0.f, 0.f);
#pragma unroll 4
    for (int rn = 0; rn < nv; rn++) {
        float w = sw[rn];
        float4 r0 = imgb[(size_t)rn * (D / 4) + base];
        float4 r1 = imgb[(size_t)rn * (D / 4) + base + 32];
        a0.x += w * r0.x; a0.y += w * r0.y; a0.z += w * r0.z; a0.w += w * r0.w;
        a1.x += w * r1.x; a1.y += w * r1.y; a1.z += w * r1.z; a1.w += w * r1.w;
    }
    float4* part = (float4*)(g_part + (size_t)(b * CHUNKS + chunk) * D);
    part[base] = a0;
    part[base + 32] = a1;
}

// ---------------- K3: merge chunk partials -> g_x; emit attention weights ---
// grid (B, 8), 256 threads = 64 positions x 4 chunk-groups (8 chunks each).
__global__ __launch_bounds__(256) void k3_merge(const int* __restrict__ len,
                                                float* __restrict__ attn_out) {
    __shared__ float sm_[CHUNKS], sl_[CHUNKS];
    __shared__ float4 sred[3][64];
    int b = blockIdx.x, ds = blockIdx.y, tid = threadIdx.x;
    int pos = tid & 63, cg = tid >> 6;
    if (tid < CHUNKS) { sm_[tid] = g_pm[b * CHUNKS + tid]; sl_[tid] = g_pl[b * CHUNKS + tid]; }
    __syncthreads();
    float M = -INFINITY;
#pragma unroll
    for (int c = 0; c < CHUNKS; c++) M = fmaxf(M, sm_[c]);
    float Lsum = 0.f;
#pragma unroll
    for (int c = 0; c < CHUNKS; c++)
        Lsum += __expf(sm_[c] - M) * sl_[c];     // exp(-inf)=0 handles empty chunks
    float invL = 1.0f / Lsum;

    int i = ds * 64 + pos;                       // float4 index into D/4=512
    float4 a = make_float4(0.f, 0.f, 0.f, 0.f);
#pragma unroll
    for (int k = 0; k < 8; k++) {                // 8 independent loads
        int c = cg * 8 + k;
        float4 p = ((const float4*)g_part)[(size_t)(b * CHUNKS + c) * (D / 4) + i];
        float f = __expf(sm_[c] - M);
        a.x += f * p.x; a.y += f * p.y; a.z += f * p.z; a.w += f * p.w;
    }
    if (cg) sred[cg - 1][pos] = a;
    __syncthreads();
    if (cg == 0) {
        float4 r0 = sred[0][pos], r1 = sred[1][pos], r2 = sred[2][pos];
        a.x = (a.x + r0.x + r1.x + r2.x) * invL;
        a.y = (a.y + r0.y + r1.y + r2.y) * invL;
        a.z = (a.z + r0.z + r1.z + r2.z) * invL;
        a.w = (a.w + r0.w + r1.w + r2.w) * invL;
        ((float4*)g_x)[b * (D / 4) + i] = a;
    }
    if (ds == 0) {
        int Lb = __ldg(&len[b]);
        for (int n = tid; n < N; n += 256)
            attn_out[b * N + n] = (n < Lb) ? __expf(g_scores[b * N + n] - M) * invL : 0.f;
    }
}

// ---------------- GEMV body: out[b,e] += sum_k A[b,k]*W[e,k] -----------------
#define KL 256
__device__ __forceinline__ void gemv32_body(const float* __restrict__ A,
                                            const float* __restrict__ W,
                                            float* __restrict__ out, int K) {
    __shared__ float sA[B * KL];
    int k0 = blockIdx.y * KL;
    for (int i = threadIdx.x; i < B * KL; i += 256) {
        int row = i >> 8, col = i & (KL - 1);
        sA[i] = A[row * K + k0 + col];
    }
    __syncthreads();
    int warp = threadIdx.x >> 5, lane = threadIdx.x & 31;
    int e = blockIdx.x * 8 + warp;
    const float4* w4 = (const float4*)(W + (size_t)e * K + k0);
    float acc[B];
#pragma unroll
    for (int b = 0; b < B; b++) acc[b] = 0.f;
#pragma unroll
    for (int j = 0; j < KL / 128; j++) {
        float4 wv = w4[lane + 32 * j];
#pragma unroll
        for (int b = 0; b < B; b++) {
            float4 a = *(const float4*)(sA + b * KL + (lane + 32 * j) * 4);
            acc[b] += wv.x * a.x + wv.y * a.y + wv.z * a.z + wv.w * a.w;
        }
    }
    float mine = 0.f;
#pragma unroll
    for (int b = 0; b < B; b++) {
        float v = acc[b];
#pragma unroll
        for (int o = 16; o; o >>= 1) v += __shfl_xor_sync(0xffffffffu, v, o);
        if (lane == b) mine = v;
    }
    atomicAdd(&out[lane * E + e], mine);
}

__global__ __launch_bounds__(256) void k5_gemv(const float* __restrict__ W) {
    gemv32_body(g_x, W, g_outfeat, D);
}
__global__ __launch_bounds__(256) void k6_gemv(const float* __restrict__ W) {
    gemv32_body(g_outfeat, W, g_feats, E);
}

// ---------------- K7: l2 normalize, write features output --------------------
__global__ __launch_bounds__(256) void k7_norm(float* __restrict__ out) {
    int b = blockIdx.x;
    __shared__ float red[8];
    int wid = threadIdx.x >> 5, lane = threadIdx.x & 31;
    float s = 0.f;
    for (int i = threadIdx.x; i < E; i += 256) {
        float v = g_feats[b * E + i];
        s += v * v;
    }
#pragma unroll
    for (int o = 16; o; o >>= 1) s += __shfl_xor_sync(0xffffffffu, s, o);
    if (lane == 0) red[wid] = s;
    __syncthreads();
    if (threadIdx.x == 0) {
        float t = 0.f;
#pragma unroll
        for (int i = 0; i < 8; i++) t += red[i];
        red[0] = 1.0f / sqrtf(t);
    }
    __syncthreads();
    float inv = red[0];
    for (int i = threadIdx.x; i < E; i += 256)
        out[b * E + i] = g_feats[b * E + i] * inv;
}

// ---------------- launch ------------------------------------------------------
extern "C" void kernel_launch(void* const* d_in, const int* in_sizes, int n_in,
                              void* d_out, int out_size) {
    const float* images = (const float*)d_in[0];  // [B,N,D]
    const float* cap    = (const float*)d_in[1];  // [B,E]
    const int*   len    = (const int*)  d_in[2];  // [B]
    const float* ws1_w  = (const float*)d_in[3];  // [E,D]
    const float* ws1_b  = (const float*)d_in[4];  // [E]
    const float* fc_w   = (const float*)d_in[5];  // [E,E]
    const float* fc_b   = (const float*)d_in[6];  // [E]
    float* out_features = (float*)d_out;          // [B,E]
    float* out_attn     = (float*)d_out + B * E;  // [B,N,1]

    // order chosen so k2_fused is the 4th launch (profiler capture slot)
    k0a_zero<<<B * D / 256, 256>>>();
    k1_v<<<dim3(4, 16, 2), 128>>>(cap, ws1_w);
    k0b_bias<<<2 * B * E / 256, 256>>>(ws1_b, fc_b);
    k2_fused<<<dim3(CHUNKS, B), 256>>>(images, len);
    k3_merge<<<dim3(B, 8), 256>>>(len, out_attn);
    k5_gemv<<<dim3(E / 8, D / KL), 256>>>(ws1_w);
    k6_gemv<<<dim3(E / 8, E / KL), 256>>>(fc_w);
    k7_norm<<<B, 256>>>(out_features);
}

// round 8
// speedup vs baseline: 1.1511x; 1.1511x over previous
#include <cuda_runtime.h>
#include <math.h>

#define B 32
#define N 1024
#define D 2048   // IMG_DIM
#define E 1024   // EMBED
#define CHUNKS 16
#define CROWS (N / CHUNKS)   // 64 rows per chunk
#define SUB 8                // rows per sub-chunk (reuse window = 64KB)

// ---------------- scratch (device globals; zero-initialized at module load).
// Invariant: g_v, g_outfeat, g_feats are ZERO on entry to kernel_launch
// (restored by k3/k7 at the end of each call).
__device__ float g_v[B * D];
__device__ float g_scores[B * N];
__device__ float g_part[B * CHUNKS * D];     // stale entries harmless (x0 weight)
__device__ float g_pm[B * CHUNKS];
__device__ float g_pl[B * CHUNKS];
__device__ float g_x[B * D];
__device__ float g_outfeat[B * E];
__device__ float g_feats[B * E];

// ---------------- K1: v[b,d] += sum_e cap[b,e]*W1[e,d]  (g_v pre-zeroed) ----
#define K1_EC 64
__global__ __launch_bounds__(128) void k1_v(const float* __restrict__ cap,
                                            const float* __restrict__ W1) {
    __shared__ float sc[16][K1_EC];
    int tid = threadIdx.x;
    int d  = blockIdx.x * 512 + tid * 4;
    int e0 = blockIdx.y * K1_EC;
    int b0 = blockIdx.z * 16;
    for (int i = tid; i < 16 * K1_EC; i += 128)
        sc[i >> 6][i & 63] = cap[(b0 + (i >> 6)) * E + e0 + (i & 63)];
    __syncthreads();
    float4 acc[16];
#pragma unroll
    for (int r = 0; r < 16; r++) acc[r] = make_float4(0.f, 0.f, 0.f, 0.f);
#pragma unroll 2
    for (int e = 0; e < K1_EC; e++) {
        float4 wv = *(const float4*)(W1 + (size_t)(e0 + e) * D + d);
#pragma unroll
        for (int r = 0; r < 16; r++) {
            float c = sc[r][e];
            acc[r].x += c * wv.x; acc[r].y += c * wv.y;
            acc[r].z += c * wv.z; acc[r].w += c * wv.w;
        }
    }
#pragma unroll
    for (int r = 0; r < 16; r++) {
        float* p = &g_v[(size_t)(b0 + r) * D + d];
        atomicAdd(p + 0, acc[r].x); atomicAdd(p + 1, acc[r].y);
        atomicAdd(p + 2, acc[r].z); atomicAdd(p + 3, acc[r].w);
    }
}

// ---------------- K2: fused scores + online softmax + pooling ---------------
// Sub-chunked so phase-2 re-reads hit L2: window = 8 rows = 64KB/block;
// 512 concurrent blocks x 64KB = 32MB << 126MB L2.
__global__ __launch_bounds__(256, 4) void k2_fused(const float* __restrict__ img,
                                                   const int* __restrict__ len) {
    __shared__ float sv[D];            // 8KB
    __shared__ float ssc[CROWS / SUB][SUB];

    int chunk = blockIdx.x, b = blockIdx.y;
    int L  = __ldg(&len[b]);
    int n0 = chunk * CROWS;
    int tid = threadIdx.x, warp = tid >> 5, lane = tid & 31;

    if (n0 >= L) {
        if (tid == 0) { g_pm[b * CHUNKS + chunk] = -INFINITY; g_pl[b * CHUNKS + chunk] = 0.f; }
        return;
    }
    int nv = min(CROWS, L - n0);

    for (int i = tid; i < D / 4; i += 256)
        ((float4*)sv)[i] = ((const float4*)g_v)[b * (D / 4) + i];
    __syncthreads();

    const float4* sv4  = (const float4*)sv;
    const float4* imgb = (const float4*)(img + ((size_t)b * N + n0) * D);
    int base = warp * 64 + lane;             // this warp's float4 slice (+32 pair)
    float4 a0 = make_float4(0.f, 0.f, 0.f, 0.f);
    float4 a1 = make_float4(0.f, 0.f, 0.f, 0.f);
    float m = -INFINITY, l = 0.f;

    for (int s = 0; s * SUB < nv; s++) {
        int rbase = s * SUB;
        int c = min(SUB, nv - rbase);
        // phase 1: warp-per-row streaming dot
        if (warp < c) {
            const float4* row = imgb + (size_t)(rbase + warp) * (D / 4);
            float dot = 0.f;
#pragma unroll
            for (int j = 0; j < 16; j++) {
                float4 r = row[j * 32 + lane];
                float4 v = sv4[j * 32 + lane];
                dot += r.x * v.x + r.y * v.y + r.z * v.z + r.w * v.w;
            }
#pragma unroll
            for (int o = 16; o; o >>= 1) dot += __shfl_xor_sync(0xffffffffu, dot, o);
            if (lane == 0) {
                ssc[s][warp] = dot;
                g_scores[b * N + n0 + rbase + warp] = dot;
            }
        }
        __syncthreads();
        // block-uniform softmax update (8-lane butterflies; groups identical)
        float sc_l = ((lane & 7) < c) ? ssc[s][lane & 7] : -INFINITY;
        float mnew = fmaxf(m, sc_l);
#pragma unroll
        for (int o = 4; o; o >>= 1) mnew = fmaxf(mnew, __shfl_xor_sync(0xffffffffu, mnew, o));
        float wexp = ((lane & 7) < c) ? __expf(sc_l - mnew) : 0.f;
        float lsub = wexp;
#pragma unroll
        for (int o = 4; o; o >>= 1) lsub += __shfl_xor_sync(0xffffffffu, lsub, o);
        if (mnew > m) {
            float scale = __expf(m - mnew);      // m=-inf first pass -> 0
            l *= scale;
            a0.x *= scale; a0.y *= scale; a0.z *= scale; a0.w *= scale;
            a1.x *= scale; a1.y *= scale; a1.z *= scale; a1.w *= scale;
            m = mnew;
        }
        l += lsub;
        // phase 2: weighted accumulate from L2-resident rows
#pragma unroll
        for (int r = 0; r < SUB; r++) {
            if (r < c) {
                float wr = __shfl_sync(0xffffffffu, wexp, r);
                float4 r0 = imgb[(size_t)(rbase + r) * (D / 4) + base];
                float4 r1 = imgb[(size_t)(rbase + r) * (D / 4) + base + 32];
                a0.x += wr * r0.x; a0.y += wr * r0.y; a0.z += wr * r0.z; a0.w += wr * r0.w;
                a1.x += wr * r1.x; a1.y += wr * r1.y; a1.z += wr * r1.z; a1.w += wr * r1.w;
            }
        }
    }

    float4* part = (float4*)(g_part + (size_t)(b * CHUNKS + chunk) * D);
    part[base] = a0;
    part[base + 32] = a1;
    if (tid == 0) { g_pm[b * CHUNKS + chunk] = m; g_pl[b * CHUNKS + chunk] = l; }
}

// ---------------- K3: merge chunk partials -> g_x; attn weights; zero g_v ---
// grid (B, 8), 256 threads = 64 positions x 4 chunk-groups (4 chunks each).
__global__ __launch_bounds__(256) void k3_merge(const int* __restrict__ len,
                                                float* __restrict__ attn_out) {
    __shared__ float sm_[CHUNKS], sl_[CHUNKS];
    __shared__ float4 sred[3][64];
    int b = blockIdx.x, ds = blockIdx.y, tid = threadIdx.x;
    int pos = tid & 63, cg = tid >> 6;
    if (tid < CHUNKS) { sm_[tid] = g_pm[b * CHUNKS + tid]; sl_[tid] = g_pl[b * CHUNKS + tid]; }
    __syncthreads();
    float M = -INFINITY;
#pragma unroll
    for (int c = 0; c < CHUNKS; c++) M = fmaxf(M, sm_[c]);
    float Lsum = 0.f;
#pragma unroll
    for (int c = 0; c < CHUNKS; c++)
        Lsum += __expf(sm_[c] - M) * sl_[c];     // exp(-inf)=0 for empty chunks
    float invL = 1.0f / Lsum;

    int i = ds * 64 + pos;                       // float4 index into D/4=512
    float4 a = make_float4(0.f, 0.f, 0.f, 0.f);
#pragma unroll
    for (int k = 0; k < 4; k++) {
        int c = cg * 4 + k;
        float4 p = ((const float4*)g_part)[(size_t)(b * CHUNKS + c) * (D / 4) + i];
        float f = __expf(sm_[c] - M);
        a.x += f * p.x; a.y += f * p.y; a.z += f * p.z; a.w += f * p.w;
    }
    if (cg) sred[cg - 1][pos] = a;
    __syncthreads();
    if (cg == 0) {
        float4 r0 = sred[0][pos], r1 = sred[1][pos], r2 = sred[2][pos];
        a.x = (a.x + r0.x + r1.x + r2.x) * invL;
        a.y = (a.y + r0.y + r1.y + r2.y) * invL;
        a.z = (a.z + r0.z + r1.z + r2.z) * invL;
        a.w = (a.w + r0.w + r1.w + r2.w) * invL;
        ((float4*)g_x)[b * (D / 4) + i] = a;
    }
    // restore invariant: zero g_v slice owned by this block (for next call)
    g_v[b * D + ds * 256 + tid] = 0.0f;
    if (ds == 0) {
        int Lb = __ldg(&len[b]);
        for (int n = tid; n < N; n += 256)
            attn_out[b * N + n] = (n < Lb) ? __expf(g_scores[b * N + n] - M) * invL : 0.f;
    }
}

// ---------------- GEMV: out[b,e] += sum_k (A[b,k]+bias[k]) * W[e,k] ----------
#define KL 256
__device__ __forceinline__ void gemv32_body(const float* __restrict__ A,
                                            const float* __restrict__ W,
                                            float* __restrict__ out, int K,
                                            const float* __restrict__ bias) {
    __shared__ float sA[B * KL];
    int k0 = blockIdx.y * KL;
    for (int i = threadIdx.x; i < B * KL; i += 256) {
        int row = i >> 8, col = i & (KL - 1);
        float v = A[row * K + k0 + col];
        if (bias) v += bias[k0 + col];
        sA[i] = v;
    }
    __syncthreads();
    int warp = threadIdx.x >> 5, lane = threadIdx.x & 31;
    int e = blockIdx.x * 8 + warp;
    const float4* w4 = (const float4*)(W + (size_t)e * K + k0);
    float acc[B];
#pragma unroll
    for (int b = 0; b < B; b++) acc[b] = 0.f;
#pragma unroll
    for (int j = 0; j < KL / 128; j++) {
        float4 wv = w4[lane + 32 * j];
#pragma unroll
        for (int b = 0; b < B; b++) {
            float4 a = *(const float4*)(sA + b * KL + (lane + 32 * j) * 4);
            acc[b] += wv.x * a.x + wv.y * a.y + wv.z * a.z + wv.w * a.w;
        }
    }
    float mine = 0.f;
#pragma unroll
    for (int b = 0; b < B; b++) {
        float v = acc[b];
#pragma unroll
        for (int o = 16; o; o >>= 1) v += __shfl_xor_sync(0xffffffffu, v, o);
        if (lane == b) mine = v;
    }
    atomicAdd(&out[lane * E + e], mine);
}

// K5: g_outfeat += g_x @ ws1_w^T (no bias fold; g_outfeat pre-zeroed)
__global__ __launch_bounds__(256) void k5_gemv(const float* __restrict__ W) {
    gemv32_body(g_x, W, g_outfeat, D, nullptr);
}
// K6: g_feats += (g_outfeat + ws1_b) @ fc_w^T (bias folded at read)
__global__ __launch_bounds__(256) void k6_gemv(const float* __restrict__ W,
                                               const float* __restrict__ ws1_b) {
    gemv32_body(g_outfeat, W, g_feats, E, ws1_b);
}

// ---------------- K7: l2-normalize (g_feats + fc_b); restore invariants ------
__global__ __launch_bounds__(256) void k7_norm(const float* __restrict__ fc_b,
                                               float* __restrict__ out) {
    int b = blockIdx.x;
    __shared__ float red[8];
    int wid = threadIdx.x >> 5, lane = threadIdx.x & 31;
    float s = 0.f;
    for (int i = threadIdx.x; i < E; i += 256) {
        float v = g_feats[b * E + i] + fc_b[i];
        s += v * v;
    }
#pragma unroll
    for (int o = 16; o; o >>= 1) s += __shfl_xor_sync(0xffffffffu, s, o);
    if (lane == 0) red[wid] = s;
    __syncthreads();
    if (threadIdx.x == 0) {
        float t = 0.f;
#pragma unroll
        for (int i = 0; i < 8; i++) t += red[i];
        red[0] = 1.0f / sqrtf(t);
    }
    __syncthreads();
    float inv = red[0];
    for (int i = threadIdx.x; i < E; i += 256) {
        out[b * E + i] = (g_feats[b * E + i] + fc_b[i]) * inv;
        g_feats[b * E + i]   = 0.0f;     // restore invariant for next call
        g_outfeat[b * E + i] = 0.0f;
    }
}

// ---------------- launch ------------------------------------------------------
extern "C" void kernel_launch(void* const* d_in, const int* in_sizes, int n_in,
                              void* d_out, int out_size) {
    const float* images = (const float*)d_in[0];  // [B,N,D]
    const float* cap    = (const float*)d_in[1];  // [B,E]
    const int*   len    = (const int*)  d_in[2];  // [B]
    const float* ws1_w  = (const float*)d_in[3];  // [E,D]
    const float* ws1_b  = (const float*)d_in[4];  // [E]
    const float* fc_w   = (const float*)d_in[5];  // [E,E]
    const float* fc_b   = (const float*)d_in[6];  // [E]
    float* out_features = (float*)d_out;          // [B,E]
    float* out_attn     = (float*)d_out + B * E;  // [B,N,1]

    k1_v<<<dim3(4, 16, 2), 128>>>(cap, ws1_w);
    k2_fused<<<dim3(CHUNKS, B), 256>>>(images, len);
    k3_merge<<<dim3(B, 8), 256>>>(len, out_attn);
    k5_gemv<<<dim3(E / 8, D / KL), 256>>>(ws1_w);
    k6_gemv<<<dim3(E / 8, E / KL), 256>>>(fc_w, ws1_b);
    k7_norm<<<B, 256>>>(fc_b, out_features);
}